// round 17
// baseline (speedup 1.0000x reference)
#include <cuda_runtime.h>

// Problem constants
#define S_LEN   512
#define HDIM    1024
#define BATCH   64
#define IDIM    1024
#define OUT_TAIL (BATCH * S_LEN * HDIM)  // offset of h_last region in d_out

typedef unsigned long long u64;

// ---- packed f32x2 helpers (SASS FFMA2 path, PTX-only) ----
__device__ __forceinline__ void unpack2(float& lo, float& hi, u64 v) {
    asm("mov.b64 {%0, %1}, %2;" : "=f"(lo), "=f"(hi) : "l"(v));
}
__device__ __forceinline__ void fma2(u64& d, u64 a, u64 b) {
    asm("fma.rn.f32x2 %0, %1, %2, %0;" : "+l"(d) : "l"(a), "l"(b));
}

// ====================================================================
// Fused persistent kernel: input projection + recurrence.
//   128 CTAs = 4 groups x 32 CTAs, 256 threads (8 warps).
//   Warp w owns K-chunk [w*128,+128).
//   Per step t:
//     1. stage x(t) k-slice into hsm (warp-private; no cross-CTA dep)
//        xp-dot into acc, streaming W_ih from L2 (depth-4 register ring)
//     2. poll REDG barrier for h(t-1)  (hidden behind phase 1)
//     3. stage h(t-1), h-dot into acc (W_hh resident in SMEM)
//     4. partials -> red, reduce + bias + relu -> out, arrive.
// ====================================================================
#define WSTR 1028                     // hsm/Wsm row stride (floats)
#define RSTR 40                       // partials: conflict-free pattern
#define RED_WSZ (16 * RSTR)           // 640 floats per warp
#define SM_H   (32 * WSTR)
#define SM_RED (48 * WSTR)
#define REC_SMEM_FLOATS (48 * WSTR + 8 * RED_WSZ)
#define REC_SMEM_BYTES  (REC_SMEM_FLOATS * 4)

__device__ unsigned g_arr[4];   // monotonic arrival counters (0 at start/end)
__device__ unsigned g_dep[4];   // departure counters for end-of-run reset

__global__ void __launch_bounds__(256, 1) rnn_kernel(
    const float* __restrict__ inputs,
    const float* __restrict__ h0,
    const float* __restrict__ Wih,
    const float* __restrict__ Whh,
    const float* __restrict__ bih,
    const float* __restrict__ bhh,
    float* out)
{
    extern __shared__ float sm[];
    float* Wsm = sm;              // [32][WSTR]  W_hh slice (persistent)
    float* hsm = sm + SM_H;       // [16][WSTR]  x(t) then h(t-1) tile
    float* red = sm + SM_RED;     // [8][16*RSTR]

    const int cta = blockIdx.x;
    const int grp = cta >> 5;        // 0..3 batch group
    const int gc  = cta & 31;        // 0..31 within group
    const int j0  = gc * 32;
    const int b0g = grp * 16;
    const int tid = threadIdx.x;
    const int w   = tid >> 5;        // warp: owns K chunk [w*128, +128)
    const int l   = tid & 31;
    const int jj  = l & 7;           // j rows: jj, jj+8, jj+16, jj+24
    const int bb  = l >> 3;          // b rows: bb, bb+4, bb+8, bb+12

    // ---- load W_hh rows [j0, j0+32) into SMEM once ----
    {
        const float4* W4 = (const float4*)Whh;
        for (int i = tid; i < 32 * 256; i += 256) {
            int r = i >> 8, c = i & 255;
            *(float4*)&Wsm[r * WSTR + c * 4] = W4[(size_t)(j0 + r) * 256 + c];
        }
    }
    __syncthreads();

    // dot-loop base pointers (k-chunk offset w*128 floats)
    const ulonglong2* wp[4];
    const ulonglong2* hp[4];
#pragma unroll
    for (int i = 0; i < 4; i++)
        wp[i] = (const ulonglong2*)(Wsm + (jj + 8 * i) * WSTR + w * 128);
#pragma unroll
    for (int m = 0; m < 4; m++)
        hp[m] = (const ulonglong2*)(hsm + (bb + 4 * m) * WSTR + w * 128);

    // W_ih stream bases: row j0+jj+8i, float4 col w*32 + kq
    const float4* WI4 = (const float4*)Wih;
    size_t wbase[4];
#pragma unroll
    for (int i = 0; i < 4; i++)
        wbase[i] = (size_t)(j0 + jj + 8 * i) * 256 + w * 32;

    // reduce-phase mapping: thread -> (b, j-pair)
    const int rb = tid >> 4;          // 0..15
    const int rj = (tid & 15) * 2;    // 0..30 even
    const int bglob_r = b0g + rb;
    const int jglob_r = j0 + rj;
    const float bs0 = bih[jglob_r]     + bhh[jglob_r];
    const float bs1 = bih[jglob_r + 1] + bhh[jglob_r + 1];

    const float4* X4 = (const float4*)inputs;   // ((b*512+t)*256 + col)

    for (int t = 0; t < S_LEN; t++) {
        // ================= PHASE 1: xp (no cross-CTA deps) =================
        // stage x(t) k-slice (16 rows x 32 f4), two chunks, warp-private
        float4 va[8], vb[8];
#pragma unroll
        for (int q = 0; q < 8; q++) {
            int f = q * 32 + l, r = f >> 4, c4 = f & 15;
            va[q] = X4[((size_t)(b0g + r) * 512 + t) * 256 + w * 32 + c4];
        }
#pragma unroll
        for (int q = 0; q < 8; q++) {
            int f = q * 32 + l, r = f >> 4, c4 = f & 15;
            vb[q] = X4[((size_t)(b0g + r) * 512 + t) * 256 + w * 32 + 16 + c4];
        }
#pragma unroll
        for (int q = 0; q < 8; q++) {
            int f = q * 32 + l, r = f >> 4, c4 = f & 15;
            *(float4*)&hsm[r * WSTR + (w * 32 + c4) * 4] = va[q];
        }
        __syncwarp();

        u64 acc[4][4];
#pragma unroll
        for (int m = 0; m < 4; m++)
#pragma unroll
            for (int i = 0; i < 4; i++) acc[m][i] = 0ull;

        // W_ih depth-4 register ring: preload kq 0..3
        float4 wbuf[4][4];
#pragma unroll
        for (int p = 0; p < 4; p++)
#pragma unroll
            for (int i = 0; i < 4; i++)
                wbuf[p][i] = WI4[wbase[i] + p];

        // xp-dot chunk A (kq 0..15; x from hsm, W_ih from ring)
#pragma unroll
        for (int kq = 0; kq < 16; kq++) {
            ulonglong2 wv[4], hv[4];
#pragma unroll
            for (int i = 0; i < 4; i++)
                wv[i] = *(const ulonglong2*)&wbuf[kq & 3][i];
#pragma unroll
            for (int m = 0; m < 4; m++) hv[m] = hp[m][kq];
            if (kq + 4 < 32) {
#pragma unroll
                for (int i = 0; i < 4; i++)
                    wbuf[kq & 3][i] = WI4[wbase[i] + kq + 4];
            }
#pragma unroll
            for (int m = 0; m < 4; m++)
#pragma unroll
                for (int i = 0; i < 4; i++) {
                    fma2(acc[m][i], wv[i].x, hv[m].x);
                    fma2(acc[m][i], wv[i].y, hv[m].y);
                }
        }
        // STS x chunk B, xp-dot chunk B (kq 16..31)
#pragma unroll
        for (int q = 0; q < 8; q++) {
            int f = q * 32 + l, r = f >> 4, c4 = f & 15;
            *(float4*)&hsm[r * WSTR + (w * 32 + 16 + c4) * 4] = vb[q];
        }
        __syncwarp();
#pragma unroll
        for (int kq = 16; kq < 32; kq++) {
            ulonglong2 wv[4], hv[4];
#pragma unroll
            for (int i = 0; i < 4; i++)
                wv[i] = *(const ulonglong2*)&wbuf[kq & 3][i];
#pragma unroll
            for (int m = 0; m < 4; m++) hv[m] = hp[m][kq];
            if (kq + 4 < 32) {
#pragma unroll
                for (int i = 0; i < 4; i++)
                    wbuf[kq & 3][i] = WI4[wbase[i] + kq + 4];
            }
#pragma unroll
            for (int m = 0; m < 4; m++)
#pragma unroll
                for (int i = 0; i < 4; i++) {
                    fma2(acc[m][i], wv[i].x, hv[m].x);
                    fma2(acc[m][i], wv[i].y, hv[m].y);
                }
        }

        // ============ PHASE 2: wait for h(t-1) (likely pre-arrived) ========
        if (t > 0) {
            if (tid == 0) {
                const unsigned want = 32u * (unsigned)t;
                while (*((volatile unsigned*)&g_arr[grp]) < want) { }
                __threadfence();                // acquire
            }
        }
        __syncthreads();   // release poll to all warps; also x-tile reads done

        // ============ PHASE 3: h staging + h-dot (R16 code) ================
        const float4* H4 = (t == 0)
            ? (const float4*)h0
            : (const float4*)(out + (size_t)(t - 1) * HDIM);
        const size_t rstride = (t == 0) ? 256u : (size_t)S_LEN * 256u;

#pragma unroll
        for (int q = 0; q < 8; q++) {          // chunk A loads
            int f = q * 32 + l, r = f >> 4, c4 = f & 15;
            va[q] = __ldcv(&H4[(size_t)(b0g + r) * rstride + w * 32 + c4]);
        }
#pragma unroll
        for (int q = 0; q < 8; q++) {          // chunk B loads (in flight)
            int f = q * 32 + l, r = f >> 4, c4 = f & 15;
            vb[q] = __ldcv(&H4[(size_t)(b0g + r) * rstride + w * 32 + 16 + c4]);
        }
#pragma unroll
        for (int q = 0; q < 8; q++) {          // STS chunk A
            int f = q * 32 + l, r = f >> 4, c4 = f & 15;
            *(float4*)&hsm[r * WSTR + (w * 32 + c4) * 4] = va[q];
        }
        __syncwarp();

        ulonglong2 wv2[2][4], hv2b[2][4];
#pragma unroll
        for (int i = 0; i < 4; i++) wv2[0][i] = wp[i][0];
#pragma unroll
        for (int m = 0; m < 4; m++) hv2b[0][m] = hp[m][0];

#pragma unroll
        for (int kq = 0; kq < 16; kq++) {
            const int cur = kq & 1;
            const int nxt = cur ^ 1;
            if (kq < 15) {
#pragma unroll
                for (int i = 0; i < 4; i++) wv2[nxt][i] = wp[i][kq + 1];
#pragma unroll
                for (int m = 0; m < 4; m++) hv2b[nxt][m] = hp[m][kq + 1];
            }
#pragma unroll
            for (int m = 0; m < 4; m++)
#pragma unroll
                for (int i = 0; i < 4; i++) {
                    fma2(acc[m][i], wv2[cur][i].x, hv2b[cur][m].x);
                    fma2(acc[m][i], wv2[cur][i].y, hv2b[cur][m].y);
                }
        }

#pragma unroll
        for (int q = 0; q < 8; q++) {          // STS chunk B
            int f = q * 32 + l, r = f >> 4, c4 = f & 15;
            *(float4*)&hsm[r * WSTR + (w * 32 + 16 + c4) * 4] = vb[q];
        }
        __syncwarp();

#pragma unroll
        for (int i = 0; i < 4; i++) wv2[0][i] = wp[i][16];
#pragma unroll
        for (int m = 0; m < 4; m++) hv2b[0][m] = hp[m][16];

#pragma unroll
        for (int kq = 16; kq < 32; kq++) {
            const int cur = kq & 1;
            const int nxt = cur ^ 1;
            if (kq < 31) {
#pragma unroll
                for (int i = 0; i < 4; i++) wv2[nxt][i] = wp[i][kq + 1];
#pragma unroll
                for (int m = 0; m < 4; m++) hv2b[nxt][m] = hp[m][kq + 1];
            }
#pragma unroll
            for (int m = 0; m < 4; m++)
#pragma unroll
                for (int i = 0; i < 4; i++) {
                    fma2(acc[m][i], wv2[cur][i].x, hv2b[cur][m].x);
                    fma2(acc[m][i], wv2[cur][i].y, hv2b[cur][m].y);
                }
        }

        // ============ PHASE 4: partials, reduce, store, arrive =============
        float* rw = red + w * RED_WSZ;
#pragma unroll
        for (int m = 0; m < 4; m++)
#pragma unroll
            for (int i = 0; i < 4; i++) {
                float lo, hi;
                unpack2(lo, hi, acc[m][i]);
                rw[(bb + 4 * m) * RSTR + (jj + 8 * i)] = lo + hi;
            }
        __syncthreads();

        float s0 = bs0, s1 = bs1;
#pragma unroll
        for (int ww = 0; ww < 8; ww++) {
            float2 p = *(const float2*)&red[ww * RED_WSZ + rb * RSTR + rj];
            s0 += p.x;
            s1 += p.y;
        }
        float2 hres = make_float2(fmaxf(s0, 0.0f), fmaxf(s1, 0.0f));
        const size_t oh = ((size_t)bglob_r * S_LEN + t) * HDIM + jglob_r;
        *(float2*)&out[oh] = hres;
        if (t == S_LEN - 1) {
            *(float2*)&out[OUT_TAIL + (size_t)bglob_r * HDIM + jglob_r] = hres;
        }
        __syncthreads();    // h stores + red reads done

        if (tid == 0) {
            __threadfence();                    // publish h_t
            atomicAdd(&g_arr[grp], 1u);         // REDG arrival (no wait here)
        }
    }

    // ---- end of run: departure count, then last observer resets to 0 ----
    if (tid == 0) {
        atomicAdd(&g_dep[grp], 1u);             // after final poll exit
        if (gc == 0) {
            while (*((volatile unsigned*)&g_dep[grp]) < 32u) { }
            *((volatile unsigned*)&g_arr[grp]) = 0u;
            *((volatile unsigned*)&g_dep[grp]) = 0u;
            __threadfence();
        }
    }
}

// ====================================================================
// Launch — single fused kernel
// ====================================================================
extern "C" void kernel_launch(void* const* d_in, const int* in_sizes, int n_in,
                              void* d_out, int out_size)
{
    const float* inputs = (const float*)d_in[0];   // [64,512,1024]
    const float* h0     = (const float*)d_in[1];   // [1,64,1024]
    const float* wih    = (const float*)d_in[2];   // [1024,1024]
    const float* whh    = (const float*)d_in[3];   // [1024,1024]
    const float* bih    = (const float*)d_in[4];   // [1024]
    const float* bhh    = (const float*)d_in[5];   // [1024]
    float* out = (float*)d_out;

    cudaFuncSetAttribute(rnn_kernel, cudaFuncAttributeMaxDynamicSharedMemorySize,
                         REC_SMEM_BYTES);
    rnn_kernel<<<128, 256, REC_SMEM_BYTES>>>(inputs, h0, wih, whh, bih, bhh, out);
}